// round 3
// baseline (speedup 1.0000x reference)
#include <cuda_runtime.h>
#include <cuda_bf16.h>
#include <math_constants.h>

// Problem constants (fixed by the dataset)
#define NN   512
#define DIN  128
#define EMAX 32768
#define HH   2
#define CC   200
#define HC   400
#define FCO  1000
#define ETOT_MAX (EMAX + NN)

// ---------------- scratch (device globals; no allocation allowed) -------------
__device__ float g_xl[NN * HC];
__device__ float g_xr[NN * HC];
__device__ float g_h [NN * HC];
__device__ int   g_deg[NN];
__device__ int   g_rowptr[NN + 1];
__device__ int   g_cursor[NN];
__device__ int   g_col[ETOT_MAX];

// ---------------- CSR build ---------------------------------------------------
__global__ void csr_zero_kernel() {
    int i = threadIdx.x;
    if (i < NN) g_deg[i] = 0;
}

__global__ void csr_count_kernel(const int* __restrict__ ei, int E) {
    int e = blockIdx.x * blockDim.x + threadIdx.x;
    int Etot = E + NN;
    if (e < Etot) {
        int dst = (e < E) ? ei[E + e] : (e - E);
        atomicAdd(&g_deg[dst], 1);
    }
}

__global__ void csr_scan_kernel() {
    __shared__ int s[NN];
    int t = threadIdx.x;
    s[t] = g_deg[t];
    __syncthreads();
    #pragma unroll
    for (int off = 1; off < NN; off <<= 1) {
        int v = (t >= off) ? s[t - off] : 0;
        __syncthreads();
        s[t] += v;
        __syncthreads();
    }
    g_rowptr[t + 1] = s[t];
    if (t == 0) g_rowptr[0] = 0;
    g_cursor[t] = (t == 0) ? 0 : s[t - 1];
}

__global__ void csr_scatter_kernel(const int* __restrict__ ei, int E) {
    int e = blockIdx.x * blockDim.x + threadIdx.x;
    int Etot = E + NN;
    if (e < Etot) {
        int dst, src;
        if (e < E) { src = ei[e]; dst = ei[E + e]; }
        else       { src = dst = e - E; }
        int p = atomicAdd(&g_cursor[dst], 1);
        g_col[p] = src;
    }
}

// ---------------- GEMM: C = A[M,K] @ B[K,HC] + bias ---------------------------
// grid: (ceil(HC/32)=13, M/32=16, 2)   z=0 -> (Wl,bl)->g_xl ; z=1 -> (Wr,br)->g_xr
// A operand: useX ? x (external input) : g_h (internal device global).
// K may be ragged (400); shared tiles are zero-padded past K.
__global__ void gemm_kernel(const float* __restrict__ Aext, int useAext,
                            const float* __restrict__ Wl, const float* __restrict__ bl,
                            const float* __restrict__ Wr, const float* __restrict__ br,
                            int K) {
    const float* A    = useAext ? Aext : g_h;
    const float* B    = blockIdx.z ? Wr : Wl;
    const float* bias = blockIdx.z ? br : bl;
    float*       Cout = blockIdx.z ? g_xr : g_xl;

    __shared__ float As[32][33];
    __shared__ float Bs[32][33];

    int tid = threadIdx.x;
    int tx = tid & 15;       // 0..15
    int ty = tid >> 4;       // 0..15
    int rowBase = blockIdx.y * 32;
    int colBase = blockIdx.x * 32;

    float acc00 = 0.f, acc01 = 0.f, acc10 = 0.f, acc11 = 0.f;

    for (int k0 = 0; k0 < K; k0 += 32) {
        #pragma unroll
        for (int i = 0; i < 4; i++) {
            int l = tid + i * 256;
            int r = l >> 5, c = l & 31;
            As[r][c] = (k0 + c < K) ? A[(rowBase + r) * K + k0 + c] : 0.f;
            int col = colBase + c;
            Bs[r][c] = (k0 + r < K && col < HC) ? B[(k0 + r) * HC + col] : 0.f;
        }
        __syncthreads();
        #pragma unroll
        for (int k = 0; k < 32; k++) {
            float a0 = As[2 * ty][k];
            float a1 = As[2 * ty + 1][k];
            float b0 = Bs[k][2 * tx];
            float b1 = Bs[k][2 * tx + 1];
            acc00 += a0 * b0; acc01 += a0 * b1;
            acc10 += a1 * b0; acc11 += a1 * b1;
        }
        __syncthreads();
    }

    int r0 = rowBase + 2 * ty;
    int c0 = colBase + 2 * tx;
    if (c0 < HC) {
        float bb = bias[c0];
        Cout[r0 * HC + c0]       = acc00 + bb;
        Cout[(r0 + 1) * HC + c0] = acc10 + bb;
    }
    if (c0 + 1 < HC) {
        float bb = bias[c0 + 1];
        Cout[r0 * HC + c0 + 1]       = acc01 + bb;
        Cout[(r0 + 1) * HC + c0 + 1] = acc11 + bb;
    }
}

// ---------------- GATv2 attention: warp per (node, head), online softmax ------
// g_h[n, h*C + c] = sum_e alpha_e * xl[src_e, h*C + c]  + bias, optional relu
__global__ void attn_kernel(const float* __restrict__ att,
                            const float* __restrict__ bias,
                            int do_relu) {
    int gwarp = (blockIdx.x * blockDim.x + threadIdx.x) >> 5;
    int lane  = threadIdx.x & 31;
    if (gwarp >= NN * HH) return;
    int n  = gwarp >> 1;
    int hh = gwarp & 1;

    const int base = hh * CC;

    float xrv[7], attv[7];
    #pragma unroll
    for (int k = 0; k < 7; k++) {
        int c = lane + 32 * k;
        bool ok = (c < CC);
        xrv[k]  = ok ? g_xr[n * HC + base + c] : 0.f;
        attv[k] = ok ? att[base + c] : 0.f;
    }

    float acc[7];
    #pragma unroll
    for (int k = 0; k < 7; k++) acc[k] = 0.f;
    float m = -CUDART_INF_F;
    float denom = 0.f;

    int e0 = g_rowptr[n];
    int e1 = g_rowptr[n + 1];

    for (int e = e0; e < e1; e++) {
        int s = g_col[e];
        const float* xls = g_xl + s * HC + base;
        float xlv[7];
        float dot = 0.f;
        #pragma unroll
        for (int k = 0; k < 7; k++) {
            int c = lane + 32 * k;
            float v = (c < CC) ? __ldg(xls + c) : 0.f;
            xlv[k] = v;
            float t = v + xrv[k];
            t = (t > 0.f) ? t : 0.2f * t;       // leaky_relu, slope 0.2
            dot = fmaf(t, attv[k], dot);
        }
        #pragma unroll
        for (int off = 16; off > 0; off >>= 1)
            dot += __shfl_xor_sync(0xffffffffu, dot, off);

        float w;
        if (dot > m) {
            float scale = (m == -CUDART_INF_F) ? 0.f : __expf(m - dot);
            #pragma unroll
            for (int k = 0; k < 7; k++) acc[k] *= scale;
            denom *= scale;
            m = dot;
            w = 1.f;
        } else {
            w = __expf(dot - m);
        }
        denom += w;
        #pragma unroll
        for (int k = 0; k < 7; k++) acc[k] = fmaf(w, xlv[k], acc[k]);
    }

    float inv = 1.f / denom;
    #pragma unroll
    for (int k = 0; k < 7; k++) {
        int c = lane + 32 * k;
        if (c < CC) {
            float v = acc[k] * inv + bias[base + c];
            if (do_relu) v = fmaxf(v, 0.f);
            g_h[n * HC + base + c] = v;
        }
    }
}

// ---------------- FC head: out = relu(flat @ fcW + fcb) -----------------------
__global__ void fc_init_kernel(float* __restrict__ out, const float* __restrict__ fcb) {
    int j = blockIdx.x * blockDim.x + threadIdx.x;
    if (j < FCO) out[j] = fcb[j];
}

// grid.x = 512 row-chunks of 400 rows each; blockDim = 256 (250 active column-float4 lanes)
__global__ void fc_gemv_kernel(const float* __restrict__ fcW, float* __restrict__ out) {
    __shared__ float sf[400];
    int tid = threadIdx.x;
    int i0 = blockIdx.x * 400;
    for (int i = tid; i < 400; i += 256) sf[i] = g_h[i0 + i];
    __syncthreads();

    if (tid < 250) {
        const float4* W4 = reinterpret_cast<const float4*>(fcW);
        float4 acc = make_float4(0.f, 0.f, 0.f, 0.f);
        #pragma unroll 4
        for (int i = 0; i < 400; i++) {
            float f = sf[i];
            float4 w = __ldg(&W4[(long)(i0 + i) * 250 + tid]);
            acc.x = fmaf(f, w.x, acc.x);
            acc.y = fmaf(f, w.y, acc.y);
            acc.z = fmaf(f, w.z, acc.z);
            acc.w = fmaf(f, w.w, acc.w);
        }
        atomicAdd(&out[4 * tid + 0], acc.x);
        atomicAdd(&out[4 * tid + 1], acc.y);
        atomicAdd(&out[4 * tid + 2], acc.z);
        atomicAdd(&out[4 * tid + 3], acc.w);
    }
}

__global__ void fc_relu_kernel(float* __restrict__ out) {
    int j = blockIdx.x * blockDim.x + threadIdx.x;
    if (j < FCO) out[j] = fmaxf(out[j], 0.f);
}

// ---------------- launch -------------------------------------------------------
extern "C" void kernel_launch(void* const* d_in, const int* in_sizes, int n_in,
                              void* d_out, int out_size) {
    const float* x   = (const float*)d_in[0];
    const int*   ei  = (const int*)  d_in[1];
    const float* Wl0 = (const float*)d_in[2];
    const float* bl0 = (const float*)d_in[3];
    const float* Wr0 = (const float*)d_in[4];
    const float* br0 = (const float*)d_in[5];
    const float* at0 = (const float*)d_in[6];
    const float* b0  = (const float*)d_in[7];
    const float* Wl1 = (const float*)d_in[8];
    const float* bl1 = (const float*)d_in[9];
    const float* Wr1 = (const float*)d_in[10];
    const float* br1 = (const float*)d_in[11];
    const float* at1 = (const float*)d_in[12];
    const float* b1  = (const float*)d_in[13];
    const float* Wl2 = (const float*)d_in[14];
    const float* bl2 = (const float*)d_in[15];
    const float* Wr2 = (const float*)d_in[16];
    const float* br2 = (const float*)d_in[17];
    const float* at2 = (const float*)d_in[18];
    const float* b2  = (const float*)d_in[19];
    const float* fcW = (const float*)d_in[20];
    const float* fcb = (const float*)d_in[21];
    float* out = (float*)d_out;

    int E = in_sizes[1] / 2;
    int Etot = E + NN;

    // CSR by destination
    csr_zero_kernel<<<1, NN>>>();
    csr_count_kernel<<<(Etot + 255) / 256, 256>>>(ei, E);
    csr_scan_kernel<<<1, NN>>>();
    csr_scatter_kernel<<<(Etot + 255) / 256, 256>>>(ei, E);

    dim3 ggrid((HC + 31) / 32, NN / 32, 2);
    dim3 agrid((NN * HH * 32 + 255) / 256);

    // layer 0 (A = x)
    gemm_kernel<<<ggrid, 256>>>(x, 1, Wl0, bl0, Wr0, br0, DIN);
    attn_kernel<<<agrid, 256>>>(at0, b0, 1);
    // layer 1 (A = g_h)
    gemm_kernel<<<ggrid, 256>>>(x, 0, Wl1, bl1, Wr1, br1, HC);
    attn_kernel<<<agrid, 256>>>(at1, b1, 1);
    // layer 2 (no relu)
    gemm_kernel<<<ggrid, 256>>>(x, 0, Wl2, bl2, Wr2, br2, HC);
    attn_kernel<<<agrid, 256>>>(at2, b2, 0);

    // FC head
    fc_init_kernel<<<(FCO + 255) / 256, 256>>>(out, fcb);
    fc_gemv_kernel<<<512, 256>>>(fcW, out);
    fc_relu_kernel<<<(FCO + 255) / 256, 256>>>(out);
}

// round 4
// speedup vs baseline: 1.0054x; 1.0054x over previous
#include <cuda_runtime.h>
#include <cuda_bf16.h>
#include <math_constants.h>

// Problem constants (fixed by the dataset)
#define NN   512
#define DIN  128
#define EMAX 32768
#define HH   2
#define CC   200
#define HC   400
#define FCO  1000
#define ETOT_MAX (EMAX + NN)

// ---------------- scratch (device globals; no allocation allowed) -------------
__device__ float g_xl[NN * HC];
__device__ float g_xr[NN * HC];
__device__ float g_h [NN * HC];
__device__ int   g_deg[NN];
__device__ int   g_rowptr[NN + 1];
__device__ int   g_cursor[NN];
__device__ int   g_col[ETOT_MAX];

// ---------------- CSR build ---------------------------------------------------
__global__ void csr_zero_kernel() {
    int i = threadIdx.x;
    if (i < NN) g_deg[i] = 0;
}

__global__ void csr_count_kernel(const int* __restrict__ ei, int E) {
    int e = blockIdx.x * blockDim.x + threadIdx.x;
    int Etot = E + NN;
    if (e < Etot) {
        int dst = (e < E) ? ei[E + e] : (e - E);
        atomicAdd(&g_deg[dst], 1);
    }
}

__global__ void csr_scan_kernel() {
    __shared__ int s[NN];
    int t = threadIdx.x;
    s[t] = g_deg[t];
    __syncthreads();
    #pragma unroll
    for (int off = 1; off < NN; off <<= 1) {
        int v = (t >= off) ? s[t - off] : 0;
        __syncthreads();
        s[t] += v;
        __syncthreads();
    }
    g_rowptr[t + 1] = s[t];
    if (t == 0) g_rowptr[0] = 0;
    g_cursor[t] = (t == 0) ? 0 : s[t - 1];
}

__global__ void csr_scatter_kernel(const int* __restrict__ ei, int E) {
    int e = blockIdx.x * blockDim.x + threadIdx.x;
    int Etot = E + NN;
    if (e < Etot) {
        int dst, src;
        if (e < E) { src = ei[e]; dst = ei[E + e]; }
        else       { src = dst = e - E; }
        int p = atomicAdd(&g_cursor[dst], 1);
        g_col[p] = src;
    }
}

// ---------------- GEMM: C = A[M,K] @ B[K,HC] + bias ---------------------------
// 64x64 tile, BK=16, 256 threads, 4x4 microtile.
// grid: (ceil(HC/64)=7, M/64=8, 2)   z=0 -> (Wl,bl)->g_xl ; z=1 -> (Wr,br)->g_xr
// K is 128 or 400: both multiples of 16 (no ragged K). Columns ragged (HC=400).
__global__ void gemm_kernel(const float* __restrict__ Aext, int useAext,
                            const float* __restrict__ Wl, const float* __restrict__ bl,
                            const float* __restrict__ Wr, const float* __restrict__ br,
                            int K) {
    const float* A    = useAext ? Aext : g_h;
    const float* B    = blockIdx.z ? Wr : Wl;
    const float* bias = blockIdx.z ? br : bl;
    float*       Cout = blockIdx.z ? g_xr : g_xl;

    __shared__ float As[16][64];   // [k][m]
    __shared__ float Bs[16][64];   // [k][n]

    const int tid = threadIdx.x;
    const int tx = tid & 15;            // n quad
    const int ty = tid >> 4;            // m quad
    const int rowBase = blockIdx.y * 64;
    const int colBase = blockIdx.x * 64;

    // loader indices
    const int a_m  = tid >> 2;          // 0..63
    const int a_k4 = (tid & 3) * 4;     // 0,4,8,12
    const int b_k  = tid >> 4;          // 0..15
    const int b_n4 = (tid & 15) * 4;    // 0..60

    float acc[4][4];
    #pragma unroll
    for (int i = 0; i < 4; i++)
        #pragma unroll
        for (int j = 0; j < 4; j++) acc[i][j] = 0.f;

    for (int k0 = 0; k0 < K; k0 += 16) {
        // A tile: 64 rows x 16 k, float4 along k
        float4 av = *reinterpret_cast<const float4*>(&A[(rowBase + a_m) * K + k0 + a_k4]);
        As[a_k4 + 0][a_m] = av.x;
        As[a_k4 + 1][a_m] = av.y;
        As[a_k4 + 2][a_m] = av.z;
        As[a_k4 + 3][a_m] = av.w;
        // B tile: 16 k x 64 n, float4 along n (guard ragged cols)
        int ncol = colBase + b_n4;
        if (ncol + 3 < HC) {
            float4 bv = *reinterpret_cast<const float4*>(&B[(k0 + b_k) * HC + ncol]);
            Bs[b_k][b_n4 + 0] = bv.x;
            Bs[b_k][b_n4 + 1] = bv.y;
            Bs[b_k][b_n4 + 2] = bv.z;
            Bs[b_k][b_n4 + 3] = bv.w;
        } else {
            #pragma unroll
            for (int j = 0; j < 4; j++)
                Bs[b_k][b_n4 + j] = (ncol + j < HC) ? B[(k0 + b_k) * HC + ncol + j] : 0.f;
        }
        __syncthreads();

        #pragma unroll
        for (int k = 0; k < 16; k++) {
            float4 a = *reinterpret_cast<const float4*>(&As[k][4 * ty]);
            float4 b = *reinterpret_cast<const float4*>(&Bs[k][4 * tx]);
            acc[0][0] = fmaf(a.x, b.x, acc[0][0]);
            acc[0][1] = fmaf(a.x, b.y, acc[0][1]);
            acc[0][2] = fmaf(a.x, b.z, acc[0][2]);
            acc[0][3] = fmaf(a.x, b.w, acc[0][3]);
            acc[1][0] = fmaf(a.y, b.x, acc[1][0]);
            acc[1][1] = fmaf(a.y, b.y, acc[1][1]);
            acc[1][2] = fmaf(a.y, b.z, acc[1][2]);
            acc[1][3] = fmaf(a.y, b.w, acc[1][3]);
            acc[2][0] = fmaf(a.z, b.x, acc[2][0]);
            acc[2][1] = fmaf(a.z, b.y, acc[2][1]);
            acc[2][2] = fmaf(a.z, b.z, acc[2][2]);
            acc[2][3] = fmaf(a.z, b.w, acc[2][3]);
            acc[3][0] = fmaf(a.w, b.x, acc[3][0]);
            acc[3][1] = fmaf(a.w, b.y, acc[3][1]);
            acc[3][2] = fmaf(a.w, b.z, acc[3][2]);
            acc[3][3] = fmaf(a.w, b.w, acc[3][3]);
        }
        __syncthreads();
    }

    const int r0 = rowBase + 4 * ty;
    const int c0 = colBase + 4 * tx;
    #pragma unroll
    for (int j = 0; j < 4; j++) {
        int c = c0 + j;
        if (c < HC) {
            float bb = bias[c];
            #pragma unroll
            for (int i = 0; i < 4; i++)
                Cout[(r0 + i) * HC + c] = acc[i][j] + bb;
        }
    }
}

// ---------------- GATv2 attention ----------------------------------------------
// One 128-thread block per (node, head). Each of 4 warps takes a strided quarter
// of the edge list with its own online-softmax state; merged through shared mem.
__global__ void attn_kernel(const float* __restrict__ att,
                            const float* __restrict__ bias,
                            int do_relu) {
    const int n    = blockIdx.x >> 1;
    const int hh   = blockIdx.x & 1;
    const int warp = threadIdx.x >> 5;
    const int lane = threadIdx.x & 31;
    const int base = hh * CC;

    __shared__ float sm_m[4];
    __shared__ float sm_d[4];
    __shared__ float sm_acc[4][CC];

    float xrv[7], attv[7];
    #pragma unroll
    for (int k = 0; k < 7; k++) {
        int c = lane + 32 * k;
        bool ok = (c < CC);
        xrv[k]  = ok ? g_xr[n * HC + base + c] : 0.f;
        attv[k] = ok ? att[base + c] : 0.f;
    }

    float acc[7];
    #pragma unroll
    for (int k = 0; k < 7; k++) acc[k] = 0.f;
    float m = -CUDART_INF_F;
    float denom = 0.f;

    const int e0 = g_rowptr[n];
    const int e1 = g_rowptr[n + 1];

    for (int e = e0 + warp; e < e1; e += 4) {
        int s = g_col[e];
        const float* xls = g_xl + s * HC + base;
        float xlv[7];
        float dot = 0.f;
        #pragma unroll
        for (int k = 0; k < 7; k++) {
            int c = lane + 32 * k;
            float v = (c < CC) ? __ldg(xls + c) : 0.f;
            xlv[k] = v;
            float t = v + xrv[k];
            t = (t > 0.f) ? t : 0.2f * t;       // leaky_relu, slope 0.2
            dot = fmaf(t, attv[k], dot);
        }
        #pragma unroll
        for (int off = 16; off > 0; off >>= 1)
            dot += __shfl_xor_sync(0xffffffffu, dot, off);

        float w;
        if (dot > m) {
            float scale = (m == -CUDART_INF_F) ? 0.f : __expf(m - dot);
            #pragma unroll
            for (int k = 0; k < 7; k++) acc[k] *= scale;
            denom *= scale;
            m = dot;
            w = 1.f;
        } else {
            w = __expf(dot - m);
        }
        denom += w;
        #pragma unroll
        for (int k = 0; k < 7; k++) acc[k] = fmaf(w, xlv[k], acc[k]);
    }

    if (lane == 0) sm_m[warp] = m;
    __syncthreads();

    float M = fmaxf(fmaxf(sm_m[0], sm_m[1]), fmaxf(sm_m[2], sm_m[3]));
    float f = __expf(m - M);                    // 0 if this warp saw no edges
    #pragma unroll
    for (int k = 0; k < 7; k++) {
        int c = lane + 32 * k;
        if (c < CC) sm_acc[warp][c] = acc[k] * f;
    }
    if (lane == 0) sm_d[warp] = denom * f;
    __syncthreads();

    float D = sm_d[0] + sm_d[1] + sm_d[2] + sm_d[3];
    float invD = 1.f / D;
    for (int c = threadIdx.x; c < CC; c += 128) {
        float v = (sm_acc[0][c] + sm_acc[1][c] + sm_acc[2][c] + sm_acc[3][c]) * invD
                  + bias[base + c];
        if (do_relu) v = fmaxf(v, 0.f);
        g_h[n * HC + base + c] = v;
    }
}

// ---------------- FC head: out = relu(flat @ fcW + fcb) -----------------------
__global__ void fc_init_kernel(float* __restrict__ out, const float* __restrict__ fcb) {
    int j = blockIdx.x * blockDim.x + threadIdx.x;
    if (j < FCO) out[j] = fcb[j];
}

// 256 blocks x 800-row chunks; 250 active column-float4 lanes per block
__global__ void fc_gemv_kernel(const float* __restrict__ fcW, float* __restrict__ out) {
    __shared__ float sf[800];
    int tid = threadIdx.x;
    int i0 = blockIdx.x * 800;
    for (int i = tid; i < 800; i += 256) sf[i] = g_h[i0 + i];
    __syncthreads();

    if (tid < 250) {
        const float4* W4 = reinterpret_cast<const float4*>(fcW);
        float4 acc = make_float4(0.f, 0.f, 0.f, 0.f);
        #pragma unroll 4
        for (int i = 0; i < 800; i++) {
            float f = sf[i];
            float4 w = __ldg(&W4[(long)(i0 + i) * 250 + tid]);
            acc.x = fmaf(f, w.x, acc.x);
            acc.y = fmaf(f, w.y, acc.y);
            acc.z = fmaf(f, w.z, acc.z);
            acc.w = fmaf(f, w.w, acc.w);
        }
        atomicAdd(&out[4 * tid + 0], acc.x);
        atomicAdd(&out[4 * tid + 1], acc.y);
        atomicAdd(&out[4 * tid + 2], acc.z);
        atomicAdd(&out[4 * tid + 3], acc.w);
    }
}

__global__ void fc_relu_kernel(float* __restrict__ out) {
    int j = blockIdx.x * blockDim.x + threadIdx.x;
    if (j < FCO) out[j] = fmaxf(out[j], 0.f);
}

// ---------------- launch -------------------------------------------------------
extern "C" void kernel_launch(void* const* d_in, const int* in_sizes, int n_in,
                              void* d_out, int out_size) {
    const float* x   = (const float*)d_in[0];
    const int*   ei  = (const int*)  d_in[1];
    const float* Wl0 = (const float*)d_in[2];
    const float* bl0 = (const float*)d_in[3];
    const float* Wr0 = (const float*)d_in[4];
    const float* br0 = (const float*)d_in[5];
    const float* at0 = (const float*)d_in[6];
    const float* b0  = (const float*)d_in[7];
    const float* Wl1 = (const float*)d_in[8];
    const float* bl1 = (const float*)d_in[9];
    const float* Wr1 = (const float*)d_in[10];
    const float* br1 = (const float*)d_in[11];
    const float* at1 = (const float*)d_in[12];
    const float* b1  = (const float*)d_in[13];
    const float* Wl2 = (const float*)d_in[14];
    const float* bl2 = (const float*)d_in[15];
    const float* Wr2 = (const float*)d_in[16];
    const float* br2 = (const float*)d_in[17];
    const float* at2 = (const float*)d_in[18];
    const float* b2  = (const float*)d_in[19];
    const float* fcW = (const float*)d_in[20];
    const float* fcb = (const float*)d_in[21];
    float* out = (float*)d_out;

    int E = in_sizes[1] / 2;
    int Etot = E + NN;

    // CSR by destination
    csr_zero_kernel<<<1, NN>>>();
    csr_count_kernel<<<(Etot + 255) / 256, 256>>>(ei, E);
    csr_scan_kernel<<<1, NN>>>();
    csr_scatter_kernel<<<(Etot + 255) / 256, 256>>>(ei, E);

    dim3 ggrid((HC + 63) / 64, NN / 64, 2);
    dim3 agrid(NN * HH);

    // layer 0 (A = x)
    gemm_kernel<<<ggrid, 256>>>(x, 1, Wl0, bl0, Wr0, br0, DIN);
    attn_kernel<<<agrid, 128>>>(at0, b0, 1);
    // layer 1 (A = g_h)
    gemm_kernel<<<ggrid, 256>>>(x, 0, Wl1, bl1, Wr1, br1, HC);
    attn_kernel<<<agrid, 128>>>(at1, b1, 1);
    // layer 2 (no relu)
    gemm_kernel<<<ggrid, 256>>>(x, 0, Wl2, bl2, Wr2, br2, HC);
    attn_kernel<<<agrid, 128>>>(at2, b2, 0);

    // FC head
    fc_init_kernel<<<(FCO + 255) / 256, 256>>>(out, fcb);
    fc_gemv_kernel<<<256, 256>>>(fcW, out);
    fc_relu_kernel<<<(FCO + 255) / 256, 256>>>(out);
}

// round 5
// speedup vs baseline: 1.1660x; 1.1598x over previous
#include <cuda_runtime.h>
#include <cuda_bf16.h>
#include <math_constants.h>

// Problem constants (fixed by the dataset)
#define NN   512
#define DIN  128
#define EMAX 32768
#define HH   2
#define CC   200
#define HC   400
#define FCO  1000
#define ETOT_MAX (EMAX + NN)

// ---------------- scratch (device globals; no allocation allowed) -------------
__device__ float g_xl[NN * HC];
__device__ float g_xr[NN * HC];
__device__ float g_h [NN * HC];
__device__ int   g_rowptr[NN + 1];
__device__ int   g_col[ETOT_MAX];
__device__ float g_fc[FCO];
__device__ int   g_ticket;

// ---------------- CSR build: single block, 512 threads ------------------------
// Also zeroes g_fc and g_ticket for the FC finisher pattern.
__global__ void csr_build_kernel(const int* __restrict__ ei, int E) {
    __shared__ int s[NN];
    __shared__ int cur[NN];
    int t = threadIdx.x;

    if (t < 500) { g_fc[t] = 0.f; g_fc[t + 500] = 0.f; }
    if (t == 0) g_ticket = 0;
    s[t] = 0;
    __syncthreads();

    int Etot = E + NN;
    for (int e = t; e < Etot; e += NN) {
        int dst = (e < E) ? ei[E + e] : (e - E);
        atomicAdd(&s[dst], 1);
    }
    __syncthreads();

    int cnt = s[t];
    #pragma unroll
    for (int off = 1; off < NN; off <<= 1) {
        int v = (t >= off) ? s[t - off] : 0;
        __syncthreads();
        s[t] += v;
        __syncthreads();
    }
    g_rowptr[t + 1] = s[t];
    if (t == 0) g_rowptr[0] = 0;
    cur[t] = s[t] - cnt;          // exclusive prefix
    __syncthreads();

    for (int e = t; e < Etot; e += NN) {
        int src, dst;
        if (e < E) { src = ei[e]; dst = ei[E + e]; }
        else       { src = dst = e - E; }
        int p = atomicAdd(&cur[dst], 1);
        g_col[p] = src;
    }
}

// ---------------- GEMM: C = A[M,K] @ B[K,HC] + bias ---------------------------
// 64x64 tile, BK=16, 256 threads, 4x4 microtile.
// grid: (7, 8, 2)   z=0 -> (Wl,bl)->g_xl ; z=1 -> (Wr,br)->g_xr
__global__ void gemm_kernel(const float* __restrict__ Aext, int useAext,
                            const float* __restrict__ Wl, const float* __restrict__ bl,
                            const float* __restrict__ Wr, const float* __restrict__ br,
                            int K) {
    const float* A    = useAext ? Aext : g_h;
    const float* B    = blockIdx.z ? Wr : Wl;
    const float* bias = blockIdx.z ? br : bl;
    float*       Cout = blockIdx.z ? g_xr : g_xl;

    __shared__ float As[16][64];   // [k][m]
    __shared__ float Bs[16][64];   // [k][n]

    const int tid = threadIdx.x;
    const int tx = tid & 15;
    const int ty = tid >> 4;
    const int rowBase = blockIdx.y * 64;
    const int colBase = blockIdx.x * 64;

    const int a_m  = tid >> 2;
    const int a_k4 = (tid & 3) * 4;
    const int b_k  = tid >> 4;
    const int b_n4 = (tid & 15) * 4;

    float acc[4][4];
    #pragma unroll
    for (int i = 0; i < 4; i++)
        #pragma unroll
        for (int j = 0; j < 4; j++) acc[i][j] = 0.f;

    for (int k0 = 0; k0 < K; k0 += 16) {
        float4 av = *reinterpret_cast<const float4*>(&A[(rowBase + a_m) * K + k0 + a_k4]);
        As[a_k4 + 0][a_m] = av.x;
        As[a_k4 + 1][a_m] = av.y;
        As[a_k4 + 2][a_m] = av.z;
        As[a_k4 + 3][a_m] = av.w;
        int ncol = colBase + b_n4;
        if (ncol + 3 < HC) {
            float4 bv = *reinterpret_cast<const float4*>(&B[(k0 + b_k) * HC + ncol]);
            Bs[b_k][b_n4 + 0] = bv.x;
            Bs[b_k][b_n4 + 1] = bv.y;
            Bs[b_k][b_n4 + 2] = bv.z;
            Bs[b_k][b_n4 + 3] = bv.w;
        } else {
            #pragma unroll
            for (int j = 0; j < 4; j++)
                Bs[b_k][b_n4 + j] = (ncol + j < HC) ? B[(k0 + b_k) * HC + ncol + j] : 0.f;
        }
        __syncthreads();

        #pragma unroll
        for (int k = 0; k < 16; k++) {
            float4 a = *reinterpret_cast<const float4*>(&As[k][4 * ty]);
            float4 b = *reinterpret_cast<const float4*>(&Bs[k][4 * tx]);
            acc[0][0] = fmaf(a.x, b.x, acc[0][0]);
            acc[0][1] = fmaf(a.x, b.y, acc[0][1]);
            acc[0][2] = fmaf(a.x, b.z, acc[0][2]);
            acc[0][3] = fmaf(a.x, b.w, acc[0][3]);
            acc[1][0] = fmaf(a.y, b.x, acc[1][0]);
            acc[1][1] = fmaf(a.y, b.y, acc[1][1]);
            acc[1][2] = fmaf(a.y, b.z, acc[1][2]);
            acc[1][3] = fmaf(a.y, b.w, acc[1][3]);
            acc[2][0] = fmaf(a.z, b.x, acc[2][0]);
            acc[2][1] = fmaf(a.z, b.y, acc[2][1]);
            acc[2][2] = fmaf(a.z, b.z, acc[2][2]);
            acc[2][3] = fmaf(a.z, b.w, acc[2][3]);
            acc[3][0] = fmaf(a.w, b.x, acc[3][0]);
            acc[3][1] = fmaf(a.w, b.y, acc[3][1]);
            acc[3][2] = fmaf(a.w, b.z, acc[3][2]);
            acc[3][3] = fmaf(a.w, b.w, acc[3][3]);
        }
        __syncthreads();
    }

    const int r0 = rowBase + 4 * ty;
    const int c0 = colBase + 4 * tx;
    #pragma unroll
    for (int j = 0; j < 4; j++) {
        int c = c0 + j;
        if (c < HC) {
            float bb = bias[c];
            #pragma unroll
            for (int i = 0; i < 4; i++)
                Cout[(r0 + i) * HC + c] = acc[i][j] + bb;
        }
    }
}

// ---------------- GATv2 attention ----------------------------------------------
// One 128-thread block per (node, head); 4 warps, strided edges, online softmax.
__global__ void attn_kernel(const float* __restrict__ att,
                            const float* __restrict__ bias,
                            int do_relu) {
    const int n    = blockIdx.x >> 1;
    const int hh   = blockIdx.x & 1;
    const int warp = threadIdx.x >> 5;
    const int lane = threadIdx.x & 31;
    const int base = hh * CC;

    __shared__ float sm_m[4];
    __shared__ float sm_d[4];
    __shared__ float sm_acc[4][CC];

    float xrv[7], attv[7];
    #pragma unroll
    for (int k = 0; k < 7; k++) {
        int c = lane + 32 * k;
        bool ok = (c < CC);
        xrv[k]  = ok ? g_xr[n * HC + base + c] : 0.f;
        attv[k] = ok ? att[base + c] : 0.f;
    }

    float acc[7];
    #pragma unroll
    for (int k = 0; k < 7; k++) acc[k] = 0.f;
    float m = -CUDART_INF_F;
    float denom = 0.f;

    const int e0 = g_rowptr[n];
    const int e1 = g_rowptr[n + 1];

    for (int e = e0 + warp; e < e1; e += 4) {
        int s = g_col[e];
        const float* xls = g_xl + s * HC + base;
        float xlv[7];
        float dot = 0.f;
        #pragma unroll
        for (int k = 0; k < 7; k++) {
            int c = lane + 32 * k;
            float v = (c < CC) ? __ldg(xls + c) : 0.f;
            xlv[k] = v;
            float t = v + xrv[k];
            t = (t > 0.f) ? t : 0.2f * t;
            dot = fmaf(t, attv[k], dot);
        }
        #pragma unroll
        for (int off = 16; off > 0; off >>= 1)
            dot += __shfl_xor_sync(0xffffffffu, dot, off);

        float w;
        if (dot > m) {
            float scale = (m == -CUDART_INF_F) ? 0.f : __expf(m - dot);
            #pragma unroll
            for (int k = 0; k < 7; k++) acc[k] *= scale;
            denom *= scale;
            m = dot;
            w = 1.f;
        } else {
            w = __expf(dot - m);
        }
        denom += w;
        #pragma unroll
        for (int k = 0; k < 7; k++) acc[k] = fmaf(w, xlv[k], acc[k]);
    }

    if (lane == 0) sm_m[warp] = m;
    __syncthreads();

    float M = fmaxf(fmaxf(sm_m[0], sm_m[1]), fmaxf(sm_m[2], sm_m[3]));
    float f = __expf(m - M);                    // 0 if this warp saw no edges
    #pragma unroll
    for (int k = 0; k < 7; k++) {
        int c = lane + 32 * k;
        if (c < CC) sm_acc[warp][c] = acc[k] * f;
    }
    if (lane == 0) sm_d[warp] = denom * f;
    __syncthreads();

    float D = sm_d[0] + sm_d[1] + sm_d[2] + sm_d[3];
    float invD = 1.f / D;
    for (int c = threadIdx.x; c < CC; c += 128) {
        float v = (sm_acc[0][c] + sm_acc[1][c] + sm_acc[2][c] + sm_acc[3][c]) * invD
                  + bias[base + c];
        if (do_relu) v = fmaxf(v, 0.f);
        g_h[n * HC + base + c] = v;
    }
}

// ---------------- FC head (single kernel, last-block finisher) -----------------
// 512 blocks x 400-row chunks; 250 active column-float4 lanes per block.
// Accumulates into g_fc via atomics; last block applies bias+relu into out.
__global__ void fc_gemv_kernel(const float* __restrict__ fcW,
                               const float* __restrict__ fcb,
                               float* __restrict__ out) {
    __shared__ float sf[400];
    __shared__ int s_old;
    int tid = threadIdx.x;
    int i0 = blockIdx.x * 400;
    for (int i = tid; i < 400; i += 256) sf[i] = g_h[i0 + i];
    __syncthreads();

    if (tid < 250) {
        const float4* W4 = reinterpret_cast<const float4*>(fcW);
        float4 acc = make_float4(0.f, 0.f, 0.f, 0.f);
        #pragma unroll 8
        for (int i = 0; i < 400; i++) {
            float f = sf[i];
            float4 w = __ldg(&W4[(long)(i0 + i) * 250 + tid]);
            acc.x = fmaf(f, w.x, acc.x);
            acc.y = fmaf(f, w.y, acc.y);
            acc.z = fmaf(f, w.z, acc.z);
            acc.w = fmaf(f, w.w, acc.w);
        }
        atomicAdd(&g_fc[4 * tid + 0], acc.x);
        atomicAdd(&g_fc[4 * tid + 1], acc.y);
        atomicAdd(&g_fc[4 * tid + 2], acc.z);
        atomicAdd(&g_fc[4 * tid + 3], acc.w);
    }
    __threadfence();
    __syncthreads();
    if (tid == 0) s_old = atomicAdd(&g_ticket, 1);
    __syncthreads();
    if (s_old == (int)gridDim.x - 1) {
        __threadfence();
        for (int j = tid; j < FCO; j += 256) {
            float v = __ldcg(&g_fc[j]) + fcb[j];
            out[j] = fmaxf(v, 0.f);
        }
    }
}

// ---------------- launch -------------------------------------------------------
extern "C" void kernel_launch(void* const* d_in, const int* in_sizes, int n_in,
                              void* d_out, int out_size) {
    const float* x   = (const float*)d_in[0];
    const int*   ei  = (const int*)  d_in[1];
    const float* Wl0 = (const float*)d_in[2];
    const float* bl0 = (const float*)d_in[3];
    const float* Wr0 = (const float*)d_in[4];
    const float* br0 = (const float*)d_in[5];
    const float* at0 = (const float*)d_in[6];
    const float* b0  = (const float*)d_in[7];
    const float* Wl1 = (const float*)d_in[8];
    const float* bl1 = (const float*)d_in[9];
    const float* Wr1 = (const float*)d_in[10];
    const float* br1 = (const float*)d_in[11];
    const float* at1 = (const float*)d_in[12];
    const float* b1  = (const float*)d_in[13];
    const float* Wl2 = (const float*)d_in[14];
    const float* bl2 = (const float*)d_in[15];
    const float* Wr2 = (const float*)d_in[16];
    const float* br2 = (const float*)d_in[17];
    const float* at2 = (const float*)d_in[18];
    const float* b2  = (const float*)d_in[19];
    const float* fcW = (const float*)d_in[20];
    const float* fcb = (const float*)d_in[21];
    float* out = (float*)d_out;

    int E = in_sizes[1] / 2;

    csr_build_kernel<<<1, NN>>>(ei, E);

    dim3 ggrid((HC + 63) / 64, NN / 64, 2);
    dim3 agrid(NN * HH);

    gemm_kernel<<<ggrid, 256>>>(x, 1, Wl0, bl0, Wr0, br0, DIN);
    attn_kernel<<<agrid, 128>>>(at0, b0, 1);
    gemm_kernel<<<ggrid, 256>>>(x, 0, Wl1, bl1, Wr1, br1, HC);
    attn_kernel<<<agrid, 128>>>(at1, b1, 1);
    gemm_kernel<<<ggrid, 256>>>(x, 0, Wl2, bl2, Wr2, br2, HC);
    attn_kernel<<<agrid, 128>>>(at2, b2, 0);

    fc_gemv_kernel<<<512, 256>>>(fcW, fcb, out);
}

// round 6
// speedup vs baseline: 1.2309x; 1.0556x over previous
#include <cuda_runtime.h>
#include <cuda_bf16.h>
#include <math_constants.h>

// Problem constants (fixed by the dataset)
#define NN   512
#define DIN  128
#define EMAX 32768
#define HH   2
#define CC   200
#define HC   400
#define FCO  1000
#define ETOT_MAX (EMAX + NN)

// ---------------- scratch (device globals; no allocation allowed) -------------
__device__ float g_xl[NN * HC];
__device__ float g_xr[NN * HC];
__device__ float g_h [NN * HC];
__device__ int   g_rowptr[NN + 1];
__device__ int   g_col[ETOT_MAX];
__device__ float g_fc[FCO];
__device__ int   g_ticket;

// ---------------- CSR build: single block, 512 threads ------------------------
__global__ void csr_build_kernel(const int* __restrict__ ei, int E) {
    __shared__ int s[NN];
    __shared__ int cur[NN];
    int t = threadIdx.x;

    if (t < 500) { g_fc[t] = 0.f; g_fc[t + 500] = 0.f; }
    if (t == 0) g_ticket = 0;
    s[t] = 0;
    __syncthreads();

    int Etot = E + NN;
    for (int e = t; e < Etot; e += NN) {
        int dst = (e < E) ? ei[E + e] : (e - E);
        atomicAdd(&s[dst], 1);
    }
    __syncthreads();

    int cnt = s[t];
    #pragma unroll
    for (int off = 1; off < NN; off <<= 1) {
        int v = (t >= off) ? s[t - off] : 0;
        __syncthreads();
        s[t] += v;
        __syncthreads();
    }
    g_rowptr[t + 1] = s[t];
    if (t == 0) g_rowptr[0] = 0;
    cur[t] = s[t] - cnt;          // exclusive prefix
    __syncthreads();

    for (int e = t; e < Etot; e += NN) {
        int src, dst;
        if (e < E) { src = ei[e]; dst = ei[E + e]; }
        else       { src = dst = e - E; }
        int p = atomicAdd(&cur[dst], 1);
        g_col[p] = src;
    }
}

// ---------------- GEMM: C = A[M,K] @ B[K,HC] + bias ---------------------------
// 32x64 tile, BK=16, 128 threads, 4x4 microtile, register double-buffering.
// grid: (7, 16, 2)   z=0 -> (Wl,bl)->g_xl ; z=1 -> (Wr,br)->g_xr
__global__ void __launch_bounds__(128)
gemm_kernel(const float* __restrict__ Aext, int useAext,
            const float* __restrict__ Wl, const float* __restrict__ bl,
            const float* __restrict__ Wr, const float* __restrict__ br,
            int K) {
    const float* A    = useAext ? Aext : g_h;
    const float* B    = blockIdx.z ? Wr : Wl;
    const float* bias = blockIdx.z ? br : bl;
    float*       Cout = blockIdx.z ? g_xr : g_xl;

    __shared__ float As[16][32];   // [k][m]
    __shared__ float Bs[16][64];   // [k][n]

    const int tid = threadIdx.x;
    const int tx = tid & 15;            // n quad: 4*tx
    const int ty = tid >> 4;            // m quad: 4*ty (0..7)
    const int rowBase = blockIdx.y * 32;
    const int colBase = blockIdx.x * 64;

    // loader indices
    const int a_m  = tid >> 2;          // 0..31
    const int a_k4 = (tid & 3) * 4;     // 0,4,8,12
    const int b_k  = tid >> 3;          // 0..15
    const int b_n8 = (tid & 7) * 8;     // 0..56

    const int nTiles = K >> 4;

    float4 pa, pb0, pb1;

    // prefetch tile 0
    {
        pa = *reinterpret_cast<const float4*>(&A[(rowBase + a_m) * K + a_k4]);
        int ncol = colBase + b_n8;
        if (ncol + 7 < HC) {
            pb0 = *reinterpret_cast<const float4*>(&B[b_k * HC + ncol]);
            pb1 = *reinterpret_cast<const float4*>(&B[b_k * HC + ncol + 4]);
        } else {
            float tmp[8];
            #pragma unroll
            for (int j = 0; j < 8; j++)
                tmp[j] = (ncol + j < HC) ? B[b_k * HC + ncol + j] : 0.f;
            pb0 = make_float4(tmp[0], tmp[1], tmp[2], tmp[3]);
            pb1 = make_float4(tmp[4], tmp[5], tmp[6], tmp[7]);
        }
    }

    float acc[4][4];
    #pragma unroll
    for (int i = 0; i < 4; i++)
        #pragma unroll
        for (int j = 0; j < 4; j++) acc[i][j] = 0.f;

    for (int t = 0; t < nTiles; t++) {
        // commit prefetched tile to smem
        As[a_k4 + 0][a_m] = pa.x;
        As[a_k4 + 1][a_m] = pa.y;
        As[a_k4 + 2][a_m] = pa.z;
        As[a_k4 + 3][a_m] = pa.w;
        *reinterpret_cast<float4*>(&Bs[b_k][b_n8])     = pb0;
        *reinterpret_cast<float4*>(&Bs[b_k][b_n8 + 4]) = pb1;
        __syncthreads();

        // prefetch next tile
        if (t + 1 < nTiles) {
            int k0 = (t + 1) << 4;
            pa = *reinterpret_cast<const float4*>(&A[(rowBase + a_m) * K + k0 + a_k4]);
            int ncol = colBase + b_n8;
            if (ncol + 7 < HC) {
                pb0 = *reinterpret_cast<const float4*>(&B[(k0 + b_k) * HC + ncol]);
                pb1 = *reinterpret_cast<const float4*>(&B[(k0 + b_k) * HC + ncol + 4]);
            } else {
                float tmp[8];
                #pragma unroll
                for (int j = 0; j < 8; j++)
                    tmp[j] = (ncol + j < HC) ? B[(k0 + b_k) * HC + ncol + j] : 0.f;
                pb0 = make_float4(tmp[0], tmp[1], tmp[2], tmp[3]);
                pb1 = make_float4(tmp[4], tmp[5], tmp[6], tmp[7]);
            }
        }

        #pragma unroll
        for (int k = 0; k < 16; k++) {
            float4 a = *reinterpret_cast<const float4*>(&As[k][4 * ty]);
            float4 b = *reinterpret_cast<const float4*>(&Bs[k][4 * tx]);
            acc[0][0] = fmaf(a.x, b.x, acc[0][0]);
            acc[0][1] = fmaf(a.x, b.y, acc[0][1]);
            acc[0][2] = fmaf(a.x, b.z, acc[0][2]);
            acc[0][3] = fmaf(a.x, b.w, acc[0][3]);
            acc[1][0] = fmaf(a.y, b.x, acc[1][0]);
            acc[1][1] = fmaf(a.y, b.y, acc[1][1]);
            acc[1][2] = fmaf(a.y, b.z, acc[1][2]);
            acc[1][3] = fmaf(a.y, b.w, acc[1][3]);
            acc[2][0] = fmaf(a.z, b.x, acc[2][0]);
            acc[2][1] = fmaf(a.z, b.y, acc[2][1]);
            acc[2][2] = fmaf(a.z, b.z, acc[2][2]);
            acc[2][3] = fmaf(a.z, b.w, acc[2][3]);
            acc[3][0] = fmaf(a.w, b.x, acc[3][0]);
            acc[3][1] = fmaf(a.w, b.y, acc[3][1]);
            acc[3][2] = fmaf(a.w, b.z, acc[3][2]);
            acc[3][3] = fmaf(a.w, b.w, acc[3][3]);
        }
        __syncthreads();
    }

    const int r0 = rowBase + 4 * ty;
    const int c0 = colBase + 4 * tx;
    #pragma unroll
    for (int j = 0; j < 4; j++) {
        int c = c0 + j;
        if (c < HC) {
            float bb = bias[c];
            #pragma unroll
            for (int i = 0; i < 4; i++)
                Cout[(r0 + i) * HC + c] = acc[i][j] + bb;
        }
    }
}

// ---------------- GATv2 attention ----------------------------------------------
// One 128-thread block per (node, head); 4 warps, strided edges, online softmax.
__global__ void attn_kernel(const float* __restrict__ att,
                            const float* __restrict__ bias,
                            int do_relu) {
    const int n    = blockIdx.x >> 1;
    const int hh   = blockIdx.x & 1;
    const int warp = threadIdx.x >> 5;
    const int lane = threadIdx.x & 31;
    const int base = hh * CC;

    __shared__ float sm_m[4];
    __shared__ float sm_d[4];
    __shared__ float sm_acc[4][CC];

    float xrv[7], attv[7];
    #pragma unroll
    for (int k = 0; k < 7; k++) {
        int c = lane + 32 * k;
        bool ok = (c < CC);
        xrv[k]  = ok ? g_xr[n * HC + base + c] : 0.f;
        attv[k] = ok ? att[base + c] : 0.f;
    }

    float acc[7];
    #pragma unroll
    for (int k = 0; k < 7; k++) acc[k] = 0.f;
    float m = -CUDART_INF_F;
    float denom = 0.f;

    const int e0 = g_rowptr[n];
    const int e1 = g_rowptr[n + 1];

    for (int e = e0 + warp; e < e1; e += 4) {
        int s = g_col[e];
        const float* xls = g_xl + s * HC + base;
        float xlv[7];
        float dot = 0.f;
        #pragma unroll
        for (int k = 0; k < 7; k++) {
            int c = lane + 32 * k;
            float v = (c < CC) ? __ldg(xls + c) : 0.f;
            xlv[k] = v;
            float t = v + xrv[k];
            t = (t > 0.f) ? t : 0.2f * t;
            dot = fmaf(t, attv[k], dot);
        }
        #pragma unroll
        for (int off = 16; off > 0; off >>= 1)
            dot += __shfl_xor_sync(0xffffffffu, dot, off);

        float w;
        if (dot > m) {
            float scale = (m == -CUDART_INF_F) ? 0.f : __expf(m - dot);
            #pragma unroll
            for (int k = 0; k < 7; k++) acc[k] *= scale;
            denom *= scale;
            m = dot;
            w = 1.f;
        } else {
            w = __expf(dot - m);
        }
        denom += w;
        #pragma unroll
        for (int k = 0; k < 7; k++) acc[k] = fmaf(w, xlv[k], acc[k]);
    }

    if (lane == 0) sm_m[warp] = m;
    __syncthreads();

    float M = fmaxf(fmaxf(sm_m[0], sm_m[1]), fmaxf(sm_m[2], sm_m[3]));
    float f = __expf(m - M);                    // 0 if this warp saw no edges
    #pragma unroll
    for (int k = 0; k < 7; k++) {
        int c = lane + 32 * k;
        if (c < CC) sm_acc[warp][c] = acc[k] * f;
    }
    if (lane == 0) sm_d[warp] = denom * f;
    __syncthreads();

    float D = sm_d[0] + sm_d[1] + sm_d[2] + sm_d[3];
    float invD = 1.f / D;
    for (int c = threadIdx.x; c < CC; c += 128) {
        float v = (sm_acc[0][c] + sm_acc[1][c] + sm_acc[2][c] + sm_acc[3][c]) * invD
                  + bias[base + c];
        if (do_relu) v = fmaxf(v, 0.f);
        g_h[n * HC + base + c] = v;
    }
}

// ---------------- FC head (single kernel, last-block finisher) -----------------
__global__ void fc_gemv_kernel(const float* __restrict__ fcW,
                               const float* __restrict__ fcb,
                               float* __restrict__ out) {
    __shared__ float sf[400];
    __shared__ int s_old;
    int tid = threadIdx.x;
    int i0 = blockIdx.x * 400;
    for (int i = tid; i < 400; i += 256) sf[i] = g_h[i0 + i];
    __syncthreads();

    if (tid < 250) {
        const float4* W4 = reinterpret_cast<const float4*>(fcW);
        float4 acc = make_float4(0.f, 0.f, 0.f, 0.f);
        #pragma unroll 8
        for (int i = 0; i < 400; i++) {
            float f = sf[i];
            float4 w = __ldg(&W4[(long)(i0 + i) * 250 + tid]);
            acc.x = fmaf(f, w.x, acc.x);
            acc.y = fmaf(f, w.y, acc.y);
            acc.z = fmaf(f, w.z, acc.z);
            acc.w = fmaf(f, w.w, acc.w);
        }
        atomicAdd(&g_fc[4 * tid + 0], acc.x);
        atomicAdd(&g_fc[4 * tid + 1], acc.y);
        atomicAdd(&g_fc[4 * tid + 2], acc.z);
        atomicAdd(&g_fc[4 * tid + 3], acc.w);
    }
    __threadfence();
    __syncthreads();
    if (tid == 0) s_old = atomicAdd(&g_ticket, 1);
    __syncthreads();
    if (s_old == (int)gridDim.x - 1) {
        __threadfence();
        for (int j = tid; j < FCO; j += 256) {
            float v = __ldcg(&g_fc[j]) + fcb[j];
            out[j] = fmaxf(v, 0.f);
        }
    }
}

// ---------------- launch -------------------------------------------------------
extern "C" void kernel_launch(void* const* d_in, const int* in_sizes, int n_in,
                              void* d_out, int out_size) {
    const float* x   = (const float*)d_in[0];
    const int*   ei  = (const int*)  d_in[1];
    const float* Wl0 = (const float*)d_in[2];
    const float* bl0 = (const float*)d_in[3];
    const float* Wr0 = (const float*)d_in[4];
    const float* br0 = (const float*)d_in[5];
    const float* at0 = (const float*)d_in[6];
    const float* b0  = (const float*)d_in[7];
    const float* Wl1 = (const float*)d_in[8];
    const float* bl1 = (const float*)d_in[9];
    const float* Wr1 = (const float*)d_in[10];
    const float* br1 = (const float*)d_in[11];
    const float* at1 = (const float*)d_in[12];
    const float* b1  = (const float*)d_in[13];
    const float* Wl2 = (const float*)d_in[14];
    const float* bl2 = (const float*)d_in[15];
    const float* Wr2 = (const float*)d_in[16];
    const float* br2 = (const float*)d_in[17];
    const float* at2 = (const float*)d_in[18];
    const float* b2  = (const float*)d_in[19];
    const float* fcW = (const float*)d_in[20];
    const float* fcb = (const float*)d_in[21];
    float* out = (float*)d_out;

    int E = in_sizes[1] / 2;

    csr_build_kernel<<<1, NN>>>(ei, E);

    dim3 ggrid((HC + 63) / 64, NN / 32, 2);
    dim3 agrid(NN * HH);

    gemm_kernel<<<ggrid, 128>>>(x, 1, Wl0, bl0, Wr0, br0, DIN);
    attn_kernel<<<agrid, 128>>>(at0, b0, 1);
    gemm_kernel<<<ggrid, 128>>>(x, 0, Wl1, bl1, Wr1, br1, HC);
    attn_kernel<<<agrid, 128>>>(at1, b1, 1);
    gemm_kernel<<<ggrid, 128>>>(x, 0, Wl2, bl2, Wr2, br2, HC);
    attn_kernel<<<agrid, 128>>>(at2, b2, 0);

    fc_gemv_kernel<<<512, 256>>>(fcW, fcb, out);
}

// round 7
// speedup vs baseline: 1.3166x; 1.0696x over previous
#include <cuda_runtime.h>
#include <cuda_bf16.h>
#include <math_constants.h>

// Problem constants (fixed by the dataset)
#define NN   512
#define DIN  128
#define EMAX 32768
#define HH   2
#define CC   200
#define HC   400
#define FCO  1000
#define ETOT_MAX (EMAX + NN)

// ---------------- scratch (device globals; no allocation allowed) -------------
__device__ float g_xl[NN * HC];
__device__ float g_xr[NN * HC];
__device__ float g_h [NN * HC];
__device__ int   g_rowptr[NN + 1];
__device__ int   g_col[ETOT_MAX];
__device__ float g_fc[FCO];
__device__ int   g_ticket;

// ---------------- CSR build: single block, 512 threads ------------------------
__global__ void csr_build_kernel(const int* __restrict__ ei, int E) {
    __shared__ int s[NN];
    __shared__ int cur[NN];
    int t = threadIdx.x;

    if (t < 500) { g_fc[t] = 0.f; g_fc[t + 500] = 0.f; }
    if (t == 0) g_ticket = 0;
    s[t] = 0;
    __syncthreads();

    int Etot = E + NN;
    for (int e = t; e < Etot; e += NN) {
        int dst = (e < E) ? ei[E + e] : (e - E);
        atomicAdd(&s[dst], 1);
    }
    __syncthreads();

    int cnt = s[t];
    #pragma unroll
    for (int off = 1; off < NN; off <<= 1) {
        int v = (t >= off) ? s[t - off] : 0;
        __syncthreads();
        s[t] += v;
        __syncthreads();
    }
    g_rowptr[t + 1] = s[t];
    if (t == 0) g_rowptr[0] = 0;
    cur[t] = s[t] - cnt;          // exclusive prefix
    __syncthreads();

    for (int e = t; e < Etot; e += NN) {
        int src, dst;
        if (e < E) { src = ei[e]; dst = ei[E + e]; }
        else       { src = dst = e - E; }
        int p = atomicAdd(&cur[dst], 1);
        g_col[p] = src;
    }
}

// ---------------- GEMM: C = A[M,K] @ B[K,HC] + bias ---------------------------
// 16x64 tile, BK=16, 128 threads, 2x4 microtile, register double-buffering.
// grid: (7, 32, 2)   z=0 -> (Wl,bl)->g_xl ; z=1 -> (Wr,br)->g_xr
__global__ void __launch_bounds__(128)
gemm_kernel(const float* __restrict__ Aext, int useAext,
            const float* __restrict__ Wl, const float* __restrict__ bl,
            const float* __restrict__ Wr, const float* __restrict__ br,
            int K) {
    const float* A    = useAext ? Aext : g_h;
    const float* B    = blockIdx.z ? Wr : Wl;
    const float* bias = blockIdx.z ? br : bl;
    float*       Cout = blockIdx.z ? g_xr : g_xl;

    __shared__ float As[16][17];   // [k][m], padded
    __shared__ float Bs[16][64];   // [k][n]

    const int tid = threadIdx.x;
    const int tx = tid & 15;            // n quad: 4*tx
    const int ty = tid >> 4;            // m pair: 2*ty (0..7 -> rows 0..15)
    const int rowBase = blockIdx.y * 16;
    const int colBase = blockIdx.x * 64;

    // loader indices
    const int a_m  = tid >> 3;          // 0..15
    const int a_k2 = (tid & 7) * 2;     // 0,2,..,14
    const int b_k  = tid >> 3;          // 0..15
    const int b_n8 = (tid & 7) * 8;     // 0..56

    const int nTiles = K >> 4;

    float2 pa;
    float4 pb0, pb1;

    // prefetch tile 0
    {
        pa = *reinterpret_cast<const float2*>(&A[(rowBase + a_m) * K + a_k2]);
        int ncol = colBase + b_n8;
        if (ncol + 7 < HC) {
            pb0 = *reinterpret_cast<const float4*>(&B[b_k * HC + ncol]);
            pb1 = *reinterpret_cast<const float4*>(&B[b_k * HC + ncol + 4]);
        } else {
            float tmp[8];
            #pragma unroll
            for (int j = 0; j < 8; j++)
                tmp[j] = (ncol + j < HC) ? B[b_k * HC + ncol + j] : 0.f;
            pb0 = make_float4(tmp[0], tmp[1], tmp[2], tmp[3]);
            pb1 = make_float4(tmp[4], tmp[5], tmp[6], tmp[7]);
        }
    }

    float acc[2][4];
    #pragma unroll
    for (int i = 0; i < 2; i++)
        #pragma unroll
        for (int j = 0; j < 4; j++) acc[i][j] = 0.f;

    for (int t = 0; t < nTiles; t++) {
        As[a_k2 + 0][a_m] = pa.x;
        As[a_k2 + 1][a_m] = pa.y;
        *reinterpret_cast<float4*>(&Bs[b_k][b_n8])     = pb0;
        *reinterpret_cast<float4*>(&Bs[b_k][b_n8 + 4]) = pb1;
        __syncthreads();

        if (t + 1 < nTiles) {
            int k0 = (t + 1) << 4;
            pa = *reinterpret_cast<const float2*>(&A[(rowBase + a_m) * K + k0 + a_k2]);
            int ncol = colBase + b_n8;
            if (ncol + 7 < HC) {
                pb0 = *reinterpret_cast<const float4*>(&B[(k0 + b_k) * HC + ncol]);
                pb1 = *reinterpret_cast<const float4*>(&B[(k0 + b_k) * HC + ncol + 4]);
            } else {
                float tmp[8];
                #pragma unroll
                for (int j = 0; j < 8; j++)
                    tmp[j] = (ncol + j < HC) ? B[(k0 + b_k) * HC + ncol + j] : 0.f;
                pb0 = make_float4(tmp[0], tmp[1], tmp[2], tmp[3]);
                pb1 = make_float4(tmp[4], tmp[5], tmp[6], tmp[7]);
            }
        }

        #pragma unroll
        for (int k = 0; k < 16; k++) {
            float a0 = As[k][2 * ty];
            float a1 = As[k][2 * ty + 1];
            float4 b = *reinterpret_cast<const float4*>(&Bs[k][4 * tx]);
            acc[0][0] = fmaf(a0, b.x, acc[0][0]);
            acc[0][1] = fmaf(a0, b.y, acc[0][1]);
            acc[0][2] = fmaf(a0, b.z, acc[0][2]);
            acc[0][3] = fmaf(a0, b.w, acc[0][3]);
            acc[1][0] = fmaf(a1, b.x, acc[1][0]);
            acc[1][1] = fmaf(a1, b.y, acc[1][1]);
            acc[1][2] = fmaf(a1, b.z, acc[1][2]);
            acc[1][3] = fmaf(a1, b.w, acc[1][3]);
        }
        __syncthreads();
    }

    const int r0 = rowBase + 2 * ty;
    const int c0 = colBase + 4 * tx;
    #pragma unroll
    for (int j = 0; j < 4; j++) {
        int c = c0 + j;
        if (c < HC) {
            float bb = bias[c];
            Cout[r0 * HC + c]       = acc[0][j] + bb;
            Cout[(r0 + 1) * HC + c] = acc[1][j] + bb;
        }
    }
}

// ---------------- GATv2 attention (layers 0,1) ---------------------------------
// One 128-thread block per (node, head); 4 warps, strided edges, online softmax.
__global__ void attn_kernel(const float* __restrict__ att,
                            const float* __restrict__ bias,
                            int do_relu) {
    const int n    = blockIdx.x >> 1;
    const int hh   = blockIdx.x & 1;
    const int warp = threadIdx.x >> 5;
    const int lane = threadIdx.x & 31;
    const int base = hh * CC;

    __shared__ float sm_m[4];
    __shared__ float sm_d[4];
    __shared__ float sm_acc[4][CC];

    float xrv[7], attv[7];
    #pragma unroll
    for (int k = 0; k < 7; k++) {
        int c = lane + 32 * k;
        bool ok = (c < CC);
        xrv[k]  = ok ? g_xr[n * HC + base + c] : 0.f;
        attv[k] = ok ? att[base + c] : 0.f;
    }

    float acc[7];
    #pragma unroll
    for (int k = 0; k < 7; k++) acc[k] = 0.f;
    float m = -CUDART_INF_F;
    float denom = 0.f;

    const int e0 = g_rowptr[n];
    const int e1 = g_rowptr[n + 1];

    for (int e = e0 + warp; e < e1; e += 4) {
        int s = g_col[e];
        const float* xls = g_xl + s * HC + base;
        float xlv[7];
        float dot = 0.f;
        #pragma unroll
        for (int k = 0; k < 7; k++) {
            int c = lane + 32 * k;
            float v = (c < CC) ? __ldg(xls + c) : 0.f;
            xlv[k] = v;
            float t = v + xrv[k];
            t = (t > 0.f) ? t : 0.2f * t;
            dot = fmaf(t, attv[k], dot);
        }
        #pragma unroll
        for (int off = 16; off > 0; off >>= 1)
            dot += __shfl_xor_sync(0xffffffffu, dot, off);

        float w;
        if (dot > m) {
            float scale = (m == -CUDART_INF_F) ? 0.f : __expf(m - dot);
            #pragma unroll
            for (int k = 0; k < 7; k++) acc[k] *= scale;
            denom *= scale;
            m = dot;
            w = 1.f;
        } else {
            w = __expf(dot - m);
        }
        denom += w;
        #pragma unroll
        for (int k = 0; k < 7; k++) acc[k] = fmaf(w, xlv[k], acc[k]);
    }

    if (lane == 0) sm_m[warp] = m;
    __syncthreads();

    float M = fmaxf(fmaxf(sm_m[0], sm_m[1]), fmaxf(sm_m[2], sm_m[3]));
    float f = __expf(m - M);
    #pragma unroll
    for (int k = 0; k < 7; k++) {
        int c = lane + 32 * k;
        if (c < CC) sm_acc[warp][c] = acc[k] * f;
    }
    if (lane == 0) sm_d[warp] = denom * f;
    __syncthreads();

    float D = sm_d[0] + sm_d[1] + sm_d[2] + sm_d[3];
    float invD = 1.f / D;
    for (int c = threadIdx.x; c < CC; c += 128) {
        float v = (sm_acc[0][c] + sm_acc[1][c] + sm_acc[2][c] + sm_acc[3][c]) * invD
                  + bias[base + c];
        if (do_relu) v = fmaxf(v, 0.f);
        g_h[n * HC + base + c] = v;
    }
}

// ---------------- Layer-2 attention fused with FC head -------------------------
// Block (n, hh) computes final h[n, base..base+199] into smem (no relu), then
// streams the 200 matching fcW rows, accumulating into g_fc. Last block applies
// bias + relu into out.
__global__ void __launch_bounds__(128)
attn_fc_kernel(const float* __restrict__ att,
               const float* __restrict__ bias,
               const float* __restrict__ fcW,
               const float* __restrict__ fcb,
               float* __restrict__ out) {
    const int n    = blockIdx.x >> 1;
    const int hh   = blockIdx.x & 1;
    const int warp = threadIdx.x >> 5;
    const int lane = threadIdx.x & 31;
    const int tid  = threadIdx.x;
    const int base = hh * CC;

    __shared__ float sm_m[4];
    __shared__ float sm_d[4];
    __shared__ float sm_acc[4][CC];
    __shared__ float sm_h[CC];
    __shared__ int s_old;

    float xrv[7], attv[7];
    #pragma unroll
    for (int k = 0; k < 7; k++) {
        int c = lane + 32 * k;
        bool ok = (c < CC);
        xrv[k]  = ok ? g_xr[n * HC + base + c] : 0.f;
        attv[k] = ok ? att[base + c] : 0.f;
    }

    float acc[7];
    #pragma unroll
    for (int k = 0; k < 7; k++) acc[k] = 0.f;
    float m = -CUDART_INF_F;
    float denom = 0.f;

    const int e0 = g_rowptr[n];
    const int e1 = g_rowptr[n + 1];

    for (int e = e0 + warp; e < e1; e += 4) {
        int s = g_col[e];
        const float* xls = g_xl + s * HC + base;
        float xlv[7];
        float dot = 0.f;
        #pragma unroll
        for (int k = 0; k < 7; k++) {
            int c = lane + 32 * k;
            float v = (c < CC) ? __ldg(xls + c) : 0.f;
            xlv[k] = v;
            float t = v + xrv[k];
            t = (t > 0.f) ? t : 0.2f * t;
            dot = fmaf(t, attv[k], dot);
        }
        #pragma unroll
        for (int off = 16; off > 0; off >>= 1)
            dot += __shfl_xor_sync(0xffffffffu, dot, off);

        float w;
        if (dot > m) {
            float scale = (m == -CUDART_INF_F) ? 0.f : __expf(m - dot);
            #pragma unroll
            for (int k = 0; k < 7; k++) acc[k] *= scale;
            denom *= scale;
            m = dot;
            w = 1.f;
        } else {
            w = __expf(dot - m);
        }
        denom += w;
        #pragma unroll
        for (int k = 0; k < 7; k++) acc[k] = fmaf(w, xlv[k], acc[k]);
    }

    if (lane == 0) sm_m[warp] = m;
    __syncthreads();

    float M = fmaxf(fmaxf(sm_m[0], sm_m[1]), fmaxf(sm_m[2], sm_m[3]));
    float f = __expf(m - M);
    #pragma unroll
    for (int k = 0; k < 7; k++) {
        int c = lane + 32 * k;
        if (c < CC) sm_acc[warp][c] = acc[k] * f;
    }
    if (lane == 0) sm_d[warp] = denom * f;
    __syncthreads();

    float D = sm_d[0] + sm_d[1] + sm_d[2] + sm_d[3];
    float invD = 1.f / D;
    for (int c = tid; c < CC; c += 128) {
        sm_h[c] = (sm_acc[0][c] + sm_acc[1][c] + sm_acc[2][c] + sm_acc[3][c]) * invD
                  + bias[base + c];
    }
    __syncthreads();

    // ---- FC part: rows (n*HC + base + r), r in [0,200) ----
    float facc[8];
    #pragma unroll
    for (int k = 0; k < 8; k++) facc[k] = 0.f;

    const float* Wrow = fcW + (long)(n * HC + base) * FCO;
    for (int r = 0; r < CC; r += 2) {
        float f0 = sm_h[r];
        float f1 = sm_h[r + 1];
        const float* w0 = Wrow + (long)r * FCO;
        const float* w1 = w0 + FCO;
        #pragma unroll
        for (int k = 0; k < 8; k++) {
            int j = tid + 128 * k;
            if (j < FCO) {
                float a = __ldg(w0 + j);
                float b = __ldg(w1 + j);
                facc[k] = fmaf(f0, a, facc[k]);
                facc[k] = fmaf(f1, b, facc[k]);
            }
        }
    }
    #pragma unroll
    for (int k = 0; k < 8; k++) {
        int j = tid + 128 * k;
        if (j < FCO) atomicAdd(&g_fc[j], facc[k]);
    }

    __threadfence();
    __syncthreads();
    if (tid == 0) s_old = atomicAdd(&g_ticket, 1);
    __syncthreads();
    if (s_old == (int)gridDim.x - 1) {
        __threadfence();
        for (int j = tid; j < FCO; j += 128) {
            float v = __ldcg(&g_fc[j]) + fcb[j];
            out[j] = fmaxf(v, 0.f);
        }
    }
}

// ---------------- launch -------------------------------------------------------
extern "C" void kernel_launch(void* const* d_in, const int* in_sizes, int n_in,
                              void* d_out, int out_size) {
    const float* x   = (const float*)d_in[0];
    const int*   ei  = (const int*)  d_in[1];
    const float* Wl0 = (const float*)d_in[2];
    const float* bl0 = (const float*)d_in[3];
    const float* Wr0 = (const float*)d_in[4];
    const float* br0 = (const float*)d_in[5];
    const float* at0 = (const float*)d_in[6];
    const float* b0  = (const float*)d_in[7];
    const float* Wl1 = (const float*)d_in[8];
    const float* bl1 = (const float*)d_in[9];
    const float* Wr1 = (const float*)d_in[10];
    const float* br1 = (const float*)d_in[11];
    const float* at1 = (const float*)d_in[12];
    const float* b1  = (const float*)d_in[13];
    const float* Wl2 = (const float*)d_in[14];
    const float* bl2 = (const float*)d_in[15];
    const float* Wr2 = (const float*)d_in[16];
    const float* br2 = (const float*)d_in[17];
    const float* at2 = (const float*)d_in[18];
    const float* b2  = (const float*)d_in[19];
    const float* fcW = (const float*)d_in[20];
    const float* fcb = (const float*)d_in[21];
    float* out = (float*)d_out;

    int E = in_sizes[1] / 2;

    csr_build_kernel<<<1, NN>>>(ei, E);

    dim3 ggrid((HC + 63) / 64, NN / 16, 2);
    dim3 agrid(NN * HH);

    gemm_kernel<<<ggrid, 128>>>(x, 1, Wl0, bl0, Wr0, br0, DIN);
    attn_kernel<<<agrid, 128>>>(at0, b0, 1);
    gemm_kernel<<<ggrid, 128>>>(x, 0, Wl1, bl1, Wr1, br1, HC);
    attn_kernel<<<agrid, 128>>>(at1, b1, 1);
    gemm_kernel<<<ggrid, 128>>>(x, 0, Wl2, bl2, Wr2, br2, HC);
    attn_fc_kernel<<<agrid, 128>>>(at2, b2, fcW, fcb, out);
}